// round 14
// baseline (speedup 1.0000x reference)
#include <cuda_runtime.h>
#include <cuda_bf16.h>
#include <math.h>
#include <stdint.h>

// ---------------------------------------------------------------------------
// DiffractionIntegration — v11 (resubmit; round-12 bench was an infra flake)
//   * ff carried as bf16 (halves the biggest DRAM stream)
//   * seg+zero fused; 3 weight transposes fused into one kernel
//   * concat folded into fn1 (split-A GEMM)
//   * accum node loop unrolled x2
//   Tall GEMMs: v10's proven bf16 mma + LDSM + fused LN/SiLU (untouched).
// ---------------------------------------------------------------------------

#define NNODE_MAX 200000
#define BMAX      256

__device__ __nv_bfloat16 g_nf [(size_t)NNODE_MAX * 256];
__device__ __nv_bfloat16 g_s1b[(size_t)NNODE_MAX * 256];
__device__ __nv_bfloat16 g_s2b[(size_t)NNODE_MAX * 128];
__device__ __nv_bfloat16 g_wt1[256 * 256];
__device__ __nv_bfloat16 g_wt2[128 * 256];
__device__ __nv_bfloat16 g_wt3[300 * 128];
__device__ __nv_bfloat16 g_ffb[(size_t)NNODE_MAX * 300];
__device__ float g_sf[BMAX * 600];
__device__ float g_d1[BMAX * 512];
__device__ float g_d2[BMAX * 256];
__device__ float g_d3[BMAX * 512];
__device__ float g_f1[BMAX * 512];
__device__ int   g_seg[BMAX + 1];

// ---------------------------------------------------------------------------
__device__ __forceinline__ void cp16(void* dst_smem, const void* src, int bytes)
{
    uint32_t d = (uint32_t)__cvta_generic_to_shared(dst_smem);
    asm volatile("cp.async.cg.shared.global [%0], [%1], 16, %2;"
                 :: "r"(d), "l"(src), "r"(bytes) : "memory");
}

__device__ __forceinline__ uint32_t smem_u32(const void* p)
{
    return (uint32_t)__cvta_generic_to_shared(p);
}

__device__ __forceinline__ void ldsm_x4(uint32_t& r0, uint32_t& r1,
                                        uint32_t& r2, uint32_t& r3, uint32_t a)
{
    asm volatile("ldmatrix.sync.aligned.m8n8.x4.shared.b16 {%0,%1,%2,%3}, [%4];"
                 : "=r"(r0), "=r"(r1), "=r"(r2), "=r"(r3) : "r"(a));
}

// ---------------------------------------------------------------------------
// bf16 GEMM (identical to v10): C = A@Wt^T + bias, optional fused LN+SiLU.
// ---------------------------------------------------------------------------
template<int BM, int BN, int WARPS_M, int WARPS_N, bool FUSE_LN, bool PRED_N,
         bool OUT_BF16>
__global__ __launch_bounds__(256, 2) void bf16_gemm(
    const __nv_bfloat16* __restrict__ A, const __nv_bfloat16* __restrict__ Wt,
    const float* __restrict__ bias, const float* __restrict__ gamma,
    const float* __restrict__ beta, void* __restrict__ Cout,
    int M, int N, int K)
{
    constexpr int BK   = 16;
    constexpr int WM   = BM / WARPS_M;
    constexpr int WN   = BN / WARPS_N;
    constexpr int MI   = WM / 16;
    constexpr int NI   = WN / 8;
    constexpr int NP   = NI / 2;
    constexpr int STR  = BK + 8;
    constexpr uint32_t A_BUF = BM * STR * 2;
    constexpr uint32_t B_BUF = BN * STR * 2;

    __shared__ __align__(16) __nv_bfloat16 As[2][BM][STR];
    __shared__ __align__(16) __nv_bfloat16 Bs[2][BN][STR];
    __shared__ float red[2][BM][WARPS_N];

    const int t    = threadIdx.x;
    const int lane = t & 31;
    const int warp = t >> 5;
    const int wm   = warp % WARPS_M;
    const int wn   = warp / WARPS_M;
    const int g    = lane >> 2;
    const int c    = lane & 3;
    const int m0   = blockIdx.y * BM;
    const int n0   = FUSE_LN ? 0 : blockIdx.x * BN;

    float acc[MI][NI][4];
#pragma unroll
    for (int mI = 0; mI < MI; ++mI)
#pragma unroll
        for (int nI = 0; nI < NI; ++nI)
#pragma unroll
            for (int r = 0; r < 4; ++r) acc[mI][nI][r] = 0.f;

    const int arow = wm * WM + (lane & 15);
    const int akc  = (lane >> 4) * 8;
    const int brow = wn * WN + (lane & 7) + ((lane >> 4) << 3);
    const int bkc  = ((lane >> 3) & 1) * 8;
    const uint32_t aBase = smem_u32(&As[0][arow][akc]);
    const uint32_t bBase = smem_u32(&Bs[0][brow][bkc]);

    auto issue_tile = [&](int kt, int buf) {
        const int k0 = kt * BK;
        if (t < BM * 2) {
            const int row = t >> 1;
            const int kc  = (t & 1) * 8;
            const int gm = m0 + row;
            const bool ok = gm < M;
            const __nv_bfloat16* src = A + (ok ? ((size_t)gm * K + k0 + kc) : 0);
            cp16(&As[buf][row][kc], src, ok ? 16 : 0);
        }
#pragma unroll
        for (int i = 0; i < (BN * 2 + 255) / 256; ++i) {
            const int s = t + i * 256;
            if (s < BN * 2) {
                const int row = s >> 1;
                const int kc  = (s & 1) * 8;
                const bool ok = (!PRED_N || (n0 + row) < N);
                const __nv_bfloat16* src =
                    Wt + (ok ? ((size_t)(n0 + row) * K + k0 + kc) : 0);
                cp16(&Bs[buf][row][kc], src, ok ? 16 : 0);
            }
        }
        asm volatile("cp.async.commit_group;" ::: "memory");
    };

    const int kTiles = K / BK;
    issue_tile(0, 0);

#pragma unroll 2
    for (int kt = 0; kt < kTiles; ++kt) {
        asm volatile("cp.async.wait_group 0;" ::: "memory");
        __syncthreads();
        if (kt + 1 < kTiles) issue_tile(kt + 1, (kt + 1) & 1);
        const uint32_t aOff = (kt & 1) ? A_BUF : 0u;
        const uint32_t bOff = (kt & 1) ? B_BUF : 0u;

        uint32_t af[MI][4], bf[NI][2];
#pragma unroll
        for (int mI = 0; mI < MI; ++mI)
            ldsm_x4(af[mI][0], af[mI][1], af[mI][2], af[mI][3],
                    aBase + aOff + (uint32_t)(mI * 16 * STR * 2));
#pragma unroll
        for (int p = 0; p < NP; ++p)
            ldsm_x4(bf[2 * p][0], bf[2 * p][1], bf[2 * p + 1][0], bf[2 * p + 1][1],
                    bBase + bOff + (uint32_t)(p * 16 * STR * 2));
#pragma unroll
        for (int mI = 0; mI < MI; ++mI)
#pragma unroll
            for (int nI = 0; nI < NI; ++nI) {
                float* d = acc[mI][nI];
                asm volatile(
                    "mma.sync.aligned.m16n8k16.row.col.f32.bf16.bf16.f32 "
                    "{%0,%1,%2,%3}, {%4,%5,%6,%7}, {%8,%9}, {%0,%1,%2,%3};"
                    : "+f"(d[0]), "+f"(d[1]), "+f"(d[2]), "+f"(d[3])
                    : "r"(af[mI][0]), "r"(af[mI][1]),
                      "r"(af[mI][2]), "r"(af[mI][3]),
                      "r"(bf[nI][0]), "r"(bf[nI][1]));
            }
    }

#pragma unroll
    for (int nI = 0; nI < NI; ++nI) {
        const int col = n0 + wn * WN + nI * 8 + 2 * c;
        float b0 = 0.f, b1 = 0.f;
        if (!PRED_N || col < N) { b0 = bias[col]; b1 = bias[col + 1]; }
#pragma unroll
        for (int mI = 0; mI < MI; ++mI) {
            acc[mI][nI][0] += b0; acc[mI][nI][1] += b1;
            acc[mI][nI][2] += b0; acc[mI][nI][3] += b1;
        }
    }

    float mean_[MI][2], rstd_[MI][2];
    if (FUSE_LN) {
#pragma unroll
        for (int mI = 0; mI < MI; ++mI)
#pragma unroll
            for (int h = 0; h < 2; ++h) {
                float s = 0.f, s2 = 0.f;
#pragma unroll
                for (int nI = 0; nI < NI; ++nI) {
                    const float v0 = acc[mI][nI][2 * h];
                    const float v1 = acc[mI][nI][2 * h + 1];
                    s += v0 + v1; s2 += v0 * v0 + v1 * v1;
                }
                s  += __shfl_xor_sync(0xffffffffu, s, 1);
                s  += __shfl_xor_sync(0xffffffffu, s, 2);
                s2 += __shfl_xor_sync(0xffffffffu, s2, 1);
                s2 += __shfl_xor_sync(0xffffffffu, s2, 2);
                if (c == 0) {
                    const int lr = wm * WM + mI * 16 + h * 8 + g;
                    red[0][lr][wn] = s;
                    red[1][lr][wn] = s2;
                }
            }
        __syncthreads();
#pragma unroll
        for (int mI = 0; mI < MI; ++mI)
#pragma unroll
            for (int h = 0; h < 2; ++h) {
                const int lr = wm * WM + mI * 16 + h * 8 + g;
                float s = 0.f, s2 = 0.f;
#pragma unroll
                for (int w = 0; w < WARPS_N; ++w) { s += red[0][lr][w]; s2 += red[1][lr][w]; }
                const float mean = s / (float)N;
                const float var  = s2 / (float)N - mean * mean;
                mean_[mI][h] = mean;
                rstd_[mI][h] = rsqrtf(var + 1e-5f);
            }
    }

#pragma unroll
    for (int nI = 0; nI < NI; ++nI) {
        const int col = n0 + wn * WN + nI * 8 + 2 * c;
        if (PRED_N && col >= N) continue;
        float ga0 = 0.f, ga1 = 0.f, be0 = 0.f, be1 = 0.f;
        if (FUSE_LN) { ga0 = gamma[col]; ga1 = gamma[col + 1];
                       be0 = beta[col];  be1 = beta[col + 1]; }
#pragma unroll
        for (int mI = 0; mI < MI; ++mI)
#pragma unroll
            for (int h = 0; h < 2; ++h) {
                const int m = m0 + wm * WM + mI * 16 + h * 8 + g;
                if (m >= M) continue;
                float v0 = acc[mI][nI][2 * h];
                float v1 = acc[mI][nI][2 * h + 1];
                if (FUSE_LN) {
                    v0 = (v0 - mean_[mI][h]) * rstd_[mI][h] * ga0 + be0;
                    v1 = (v1 - mean_[mI][h]) * rstd_[mI][h] * ga1 + be1;
                    v0 = v0 / (1.f + __expf(-v0));
                    v1 = v1 / (1.f + __expf(-v1));
                }
                if (OUT_BF16) {
                    __nv_bfloat162 o = __floats2bfloat162_rn(v0, v1);
                    *reinterpret_cast<__nv_bfloat162*>(
                        &((__nv_bfloat16*)Cout)[(size_t)m * N + col]) = o;
                } else {
                    *reinterpret_cast<float2*>(
                        &((float*)Cout)[(size_t)m * N + col]) = make_float2(v0, v1);
                }
            }
    }
}

// ---------------------------------------------------------------------------
__global__ void f32_to_bf16_kernel(const float* __restrict__ in,
                                   __nv_bfloat16* __restrict__ out, size_t n)
{
    const size_t i = ((size_t)blockIdx.x * blockDim.x + threadIdx.x) * 2;
    if (i < n) {
        float2 v = *reinterpret_cast<const float2*>(&in[i]);
        *reinterpret_cast<__nv_bfloat162*>(&out[i]) = __floats2bfloat162_rn(v.x, v.y);
    }
}

// All three weight transposes in one launch.
__global__ void conv_all_kernel(const float* __restrict__ w1,
                                const float* __restrict__ w2,
                                const float* __restrict__ w3,
                                __nv_bfloat16* __restrict__ wt1,
                                __nv_bfloat16* __restrict__ wt2,
                                __nv_bfloat16* __restrict__ wt3)
{
    const int idx = blockIdx.x * blockDim.x + threadIdx.x;
    if (idx < 256 * 256) {
        const int k = idx >> 8, n = idx & 255;
        wt1[n * 256 + k] = __float2bfloat16(w1[idx]);
    } else if (idx < 256 * 256 + 256 * 128) {
        const int i = idx - 256 * 256;
        const int k = i >> 7, n = i & 127;
        wt2[n * 256 + k] = __float2bfloat16(w2[i]);
    } else if (idx < 256 * 256 + 256 * 128 + 128 * 300) {
        const int i = idx - (256 * 256 + 256 * 128);
        const int k = i / 300, n = i % 300;
        wt3[n * 128 + k] = __float2bfloat16(w3[i]);
    }
}

// seg + sf zeroing in one launch.
__global__ void prologue_kernel(const int* __restrict__ batch, int N, int B,
                                float* __restrict__ sf, int sfn)
{
    const int i = blockIdx.x * blockDim.x + threadIdx.x;
    if (i < sfn) sf[i] = 0.f;
    if (i <= B) {
        int lo = 0, hi = N;
        while (lo < hi) {
            int mid = (lo + hi) >> 1;
            if (batch[mid] < i) lo = mid + 1; else hi = mid;
        }
        g_seg[i] = lo;
    }
}

// ---------------------------------------------------------------------------
// Small SGEMM (B=256 rows): 64x64, BK=16, 4x4 microtile. Optional split-A.
// ---------------------------------------------------------------------------
__global__ __launch_bounds__(256) void sgemm_small(
    const float* __restrict__ A, const float* __restrict__ A2, int K1,
    const float* __restrict__ W,
    const float* __restrict__ bias, const float* __restrict__ residual,
    float* __restrict__ C, int M, int N, int K)
{
    __shared__ float As[16][64];
    __shared__ float Bs[16][68];

    const int t  = threadIdx.x;
    const int tx = t & 15;
    const int ty = t >> 4;
    const int n0 = blockIdx.x * 64;
    const int m0 = blockIdx.y * 64;
    const int K2 = K - K1;

    float acc[4][4];
#pragma unroll
    for (int i = 0; i < 4; ++i)
#pragma unroll
        for (int j = 0; j < 4; ++j) acc[i][j] = 0.f;

    const int kTiles = (K + 15) / 16;
    for (int kt = 0; kt < kTiles; ++kt) {
        const int k0 = kt * 16;
        {
            const int row = t >> 2;
            const int c4  = (t & 3) * 4;
            const int gm = m0 + row, gk = k0 + c4;
            float4 v = make_float4(0.f,0.f,0.f,0.f);
            if (gm < M && gk < K) {
                if (gk < K1)
                    v = *reinterpret_cast<const float4*>(&A[(size_t)gm * K1 + gk]);
                else
                    v = *reinterpret_cast<const float4*>(&A2[(size_t)gm * K2 + (gk - K1)]);
            }
            As[c4 + 0][row] = v.x; As[c4 + 1][row] = v.y;
            As[c4 + 2][row] = v.z; As[c4 + 3][row] = v.w;
        }
        {
            const int rowk = t >> 4;
            const int c4   = (t & 15) * 4;
            const int gk = k0 + rowk, gn = n0 + c4;
            float4 v = make_float4(0.f,0.f,0.f,0.f);
            if (gk < K && gn < N)
                v = *reinterpret_cast<const float4*>(&W[(size_t)gk * N + gn]);
            *reinterpret_cast<float4*>(&Bs[rowk][c4]) = v;
        }
        __syncthreads();

#pragma unroll
        for (int kk = 0; kk < 16; ++kk) {
            float4 av = *reinterpret_cast<const float4*>(&As[kk][ty * 4]);
            float4 bv = *reinterpret_cast<const float4*>(&Bs[kk][tx * 4]);
            float a[4] = {av.x,av.y,av.z,av.w};
            float b[4] = {bv.x,bv.y,bv.z,bv.w};
#pragma unroll
            for (int i = 0; i < 4; ++i)
#pragma unroll
                for (int j = 0; j < 4; ++j)
                    acc[i][j] = fmaf(a[i], b[j], acc[i][j]);
        }
        __syncthreads();
    }

#pragma unroll
    for (int i = 0; i < 4; ++i) {
        const int m = m0 + ty * 4 + i;
        if (m >= M) continue;
#pragma unroll
        for (int j = 0; j < 4; ++j) {
            const int n = n0 + tx * 4 + j;
            if (n >= N) continue;
            float v = acc[i][j] + bias[n];
            if (residual) v += residual[(size_t)m * N + n];
            C[(size_t)m * N + n] = v;
        }
    }
}

// ---------------------------------------------------------------------------
__global__ void ln_silu_kernel(float* __restrict__ X, const float* __restrict__ g,
                               const float* __restrict__ b, int W, int do_silu)
{
    const int row = blockIdx.x;
    const int t = threadIdx.x;
    const int lane = t & 31, warp = t >> 5, nw = W >> 5;
    __shared__ float red[16];

    float x = X[(size_t)row * W + t];

    float s = x;
#pragma unroll
    for (int o = 16; o > 0; o >>= 1) s += __shfl_xor_sync(0xffffffffu, s, o);
    if (lane == 0) red[warp] = s;
    __syncthreads();
    float v = (lane < nw) ? red[lane] : 0.f;
#pragma unroll
    for (int o = 16; o > 0; o >>= 1) v += __shfl_xor_sync(0xffffffffu, v, o);
    const float mean = v / (float)W;
    __syncthreads();

    const float dx = x - mean;
    float s2 = dx * dx;
#pragma unroll
    for (int o = 16; o > 0; o >>= 1) s2 += __shfl_xor_sync(0xffffffffu, s2, o);
    if (lane == 0) red[warp] = s2;
    __syncthreads();
    float v2 = (lane < nw) ? red[lane] : 0.f;
#pragma unroll
    for (int o = 16; o > 0; o >>= 1) v2 += __shfl_xor_sync(0xffffffffu, v2, o);
    const float var = v2 / (float)W;

    float y = dx * rsqrtf(var + 1e-5f) * g[t] + b[t];
    if (do_silu) y = y * (1.0f / (1.0f + expf(-y)));
    X[(size_t)row * W + t] = y;
}

// ---------------------------------------------------------------------------
// Structure-factor accumulation; ff in bf16; node loop unrolled x2.
// ---------------------------------------------------------------------------
__global__ void accum_kernel(const __nv_bfloat16* __restrict__ ff,
                             const float* __restrict__ pos,
                             const float* __restrict__ hkl,
                             float* __restrict__ sf, int nchunks)
{
    const int b = blockIdx.x;
    const int chunk = blockIdx.y;
    const int j = threadIdx.x;
    if (j >= 300) return;

    const int s = g_seg[b], e = g_seg[b + 1];
    const int len = e - s;
    if (len <= 0) return;
    const int per = (len + nchunks - 1) / nchunks;
    const int n0 = s + chunk * per;
    const int n1 = (n0 + per < e) ? (n0 + per) : e;
    if (n0 >= e) return;

    const float hx = hkl[j * 3 + 0], hy = hkl[j * 3 + 1], hz = hkl[j * 3 + 2];
    float rj = 0.f, ij = 0.f;
    const float TWO_PI = 6.283185307179586f;

    int n = n0;
    for (; n + 1 < n1; n += 2) {
        const float px0 = __ldg(&pos[n * 3 + 0]);
        const float py0 = __ldg(&pos[n * 3 + 1]);
        const float pz0 = __ldg(&pos[n * 3 + 2]);
        const float px1 = __ldg(&pos[n * 3 + 3]);
        const float py1 = __ldg(&pos[n * 3 + 4]);
        const float pz1 = __ldg(&pos[n * 3 + 5]);
        const float f0 = __bfloat162float(ff[(size_t)n * 300 + j]);
        const float f1 = __bfloat162float(ff[(size_t)(n + 1) * 300 + j]);
        float d0 = fmaf(px0, hx, fmaf(py0, hy, pz0 * hz));
        float d1 = fmaf(px1, hx, fmaf(py1, hy, pz1 * hz));
        d0 -= rintf(d0);
        d1 -= rintf(d1);
        float sn0, cs0, sn1, cs1;
        __sincosf(TWO_PI * d0, &sn0, &cs0);
        __sincosf(TWO_PI * d1, &sn1, &cs1);
        rj = fmaf(f0, cs0, rj); ij = fmaf(f0, sn0, ij);
        rj = fmaf(f1, cs1, rj); ij = fmaf(f1, sn1, ij);
    }
    if (n < n1) {
        const float px = __ldg(&pos[n * 3 + 0]);
        const float py = __ldg(&pos[n * 3 + 1]);
        const float pz = __ldg(&pos[n * 3 + 2]);
        const float f = __bfloat162float(ff[(size_t)n * 300 + j]);
        float d = fmaf(px, hx, fmaf(py, hy, pz * hz));
        d -= rintf(d);
        float sn, cs;
        __sincosf(TWO_PI * d, &sn, &cs);
        rj = fmaf(f, cs, rj);
        ij = fmaf(f, sn, ij);
    }
    atomicAdd(&sf[b * 600 + 2 * j + 0], rj);
    atomicAdd(&sf[b * 600 + 2 * j + 1], ij);
}

// ---------------------------------------------------------------------------
extern "C" void kernel_launch(void* const* d_in, const int* in_sizes, int n_in,
                              void* d_out, int out_size)
{
    const float* graph  = (const float*)d_in[0];
    const float* nodef  = (const float*)d_in[1];
    const float* pos    = (const float*)d_in[2];
    const int*   batch  = (const int*)  d_in[3];
    const float* hkl    = (const float*)d_in[4];
    const float* ff_w1  = (const float*)d_in[5];
    const float* ff_b1  = (const float*)d_in[6];
    const float* ff_g1  = (const float*)d_in[7];
    const float* ff_bb1 = (const float*)d_in[8];
    const float* ff_w2  = (const float*)d_in[9];
    const float* ff_b2  = (const float*)d_in[10];
    const float* ff_g2  = (const float*)d_in[11];
    const float* ff_bb2 = (const float*)d_in[12];
    const float* ff_w3  = (const float*)d_in[13];
    const float* ff_b3  = (const float*)d_in[14];
    const float* dn_w1  = (const float*)d_in[15];
    const float* dn_b1  = (const float*)d_in[16];
    const float* dn_g1  = (const float*)d_in[17];
    const float* dn_bb1 = (const float*)d_in[18];
    const float* dn_w2  = (const float*)d_in[19];
    const float* dn_b2  = (const float*)d_in[20];
    const float* dn_g2  = (const float*)d_in[21];
    const float* dn_bb2 = (const float*)d_in[22];
    const float* dn_w3  = (const float*)d_in[23];
    const float* dn_b3  = (const float*)d_in[24];
    const float* fn_w1  = (const float*)d_in[25];
    const float* fn_b1  = (const float*)d_in[26];
    const float* fn_g   = (const float*)d_in[27];
    const float* fn_bb  = (const float*)d_in[28];
    const float* fn_w2  = (const float*)d_in[29];
    const float* fn_b2  = (const float*)d_in[30];
    float* out = (float*)d_out;

    const int N = in_sizes[3];
    const int B = in_sizes[0] / 512;

    __nv_bfloat16 *nf, *s1b, *s2b, *wt1, *wt2, *wt3, *ffb;
    float *sf, *dd1, *dd2, *dd3, *f1;
    cudaGetSymbolAddress((void**)&nf,   g_nf);
    cudaGetSymbolAddress((void**)&s1b,  g_s1b);
    cudaGetSymbolAddress((void**)&s2b,  g_s2b);
    cudaGetSymbolAddress((void**)&wt1,  g_wt1);
    cudaGetSymbolAddress((void**)&wt2,  g_wt2);
    cudaGetSymbolAddress((void**)&wt3,  g_wt3);
    cudaGetSymbolAddress((void**)&ffb,  g_ffb);
    cudaGetSymbolAddress((void**)&sf,   g_sf);
    cudaGetSymbolAddress((void**)&dd1,  g_d1);
    cudaGetSymbolAddress((void**)&dd2,  g_d2);
    cudaGetSymbolAddress((void**)&dd3,  g_d3);
    cudaGetSymbolAddress((void**)&f1,   g_f1);

    const int gy = (N + 63) / 64;
    const size_t nfe = (size_t)N * 256;

    // --- prologue (3 launches) ---
    f32_to_bf16_kernel<<<(int)((nfe / 2 + 255) / 256), 256>>>(nodef, nf, nfe);
    const int conv_total = 256 * 256 + 256 * 128 + 128 * 300;
    conv_all_kernel<<<(conv_total + 255) / 256, 256>>>(ff_w1, ff_w2, ff_w3,
                                                       wt1, wt2, wt3);
    prologue_kernel<<<(B * 600 + 255) / 256, 256>>>(batch, N, B, sf, B * 600);

    // --- node MLP (v10 path, unchanged) ---
    bf16_gemm<64, 256, 2, 4, true,  false, true ><<<dim3(1, gy), 256>>>(
        nf,  wt1, ff_b1, ff_g1, ff_bb1, s1b, N, 256, 256);
    bf16_gemm<64, 128, 4, 2, true,  false, true ><<<dim3(1, gy), 256>>>(
        s1b, wt2, ff_b2, ff_g2, ff_bb2, s2b, N, 128, 256);
    bf16_gemm<64, 64,  4, 2, false, true,  true ><<<dim3(5, gy), 256>>>(
        s2b, wt3, ff_b3, nullptr, nullptr, ffb, N, 300, 128);

    // --- structure factors (ff in bf16) ---
    const int CHUNKS = 8;
    accum_kernel<<<dim3(B, CHUNKS), 320>>>(ffb, pos, hkl, sf, CHUNKS);

    // --- diffraction net (B rows) ---
    sgemm_small<<<dim3(8, (B + 63) / 64), 256>>>(sf, nullptr, 600,
        dn_w1, dn_b1, nullptr, dd1, B, 512, 600);
    ln_silu_kernel<<<B, 512>>>(dd1, dn_g1, dn_bb1, 512, 1);
    sgemm_small<<<dim3(4, (B + 63) / 64), 256>>>(dd1, nullptr, 512,
        dn_w2, dn_b2, nullptr, dd2, B, 256, 512);
    ln_silu_kernel<<<B, 256>>>(dd2, dn_g2, dn_bb2, 256, 1);
    sgemm_small<<<dim3(8, (B + 63) / 64), 256>>>(dd2, nullptr, 256,
        dn_w3, dn_b3, nullptr, dd3, B, 512, 256);

    // --- fusion net: concat folded in (split-A), then LN, then final+res ---
    sgemm_small<<<dim3(8, (B + 63) / 64), 256>>>(graph, dd3, 512,
        fn_w1, fn_b1, nullptr, f1, B, 512, 1024);
    ln_silu_kernel<<<B, 512>>>(f1, fn_g, fn_bb, 512, 1);
    sgemm_small<<<dim3(8, (B + 63) / 64), 256>>>(f1, nullptr, 512,
        fn_w2, fn_b2, graph, out, B, 512, 512);
}

// round 15
// speedup vs baseline: 1.0094x; 1.0094x over previous
#include <cuda_runtime.h>
#include <cuda_bf16.h>
#include <math.h>
#include <stdint.h>

// ---------------------------------------------------------------------------
// DiffractionIntegration — v11 (resubmit; round-12 bench was an infra flake)
//   * ff carried as bf16 (halves the biggest DRAM stream)
//   * seg+zero fused; 3 weight transposes fused into one kernel
//   * concat folded into fn1 (split-A GEMM)
//   * accum node loop unrolled x2
//   Tall GEMMs: v10's proven bf16 mma + LDSM + fused LN/SiLU (untouched).
// ---------------------------------------------------------------------------

#define NNODE_MAX 200000
#define BMAX      256

__device__ __nv_bfloat16 g_nf [(size_t)NNODE_MAX * 256];
__device__ __nv_bfloat16 g_s1b[(size_t)NNODE_MAX * 256];
__device__ __nv_bfloat16 g_s2b[(size_t)NNODE_MAX * 128];
__device__ __nv_bfloat16 g_wt1[256 * 256];
__device__ __nv_bfloat16 g_wt2[128 * 256];
__device__ __nv_bfloat16 g_wt3[300 * 128];
__device__ __nv_bfloat16 g_ffb[(size_t)NNODE_MAX * 300];
__device__ float g_sf[BMAX * 600];
__device__ float g_d1[BMAX * 512];
__device__ float g_d2[BMAX * 256];
__device__ float g_d3[BMAX * 512];
__device__ float g_f1[BMAX * 512];
__device__ int   g_seg[BMAX + 1];

// ---------------------------------------------------------------------------
__device__ __forceinline__ void cp16(void* dst_smem, const void* src, int bytes)
{
    uint32_t d = (uint32_t)__cvta_generic_to_shared(dst_smem);
    asm volatile("cp.async.cg.shared.global [%0], [%1], 16, %2;"
                 :: "r"(d), "l"(src), "r"(bytes) : "memory");
}

__device__ __forceinline__ uint32_t smem_u32(const void* p)
{
    return (uint32_t)__cvta_generic_to_shared(p);
}

__device__ __forceinline__ void ldsm_x4(uint32_t& r0, uint32_t& r1,
                                        uint32_t& r2, uint32_t& r3, uint32_t a)
{
    asm volatile("ldmatrix.sync.aligned.m8n8.x4.shared.b16 {%0,%1,%2,%3}, [%4];"
                 : "=r"(r0), "=r"(r1), "=r"(r2), "=r"(r3) : "r"(a));
}

// ---------------------------------------------------------------------------
// bf16 GEMM (identical to v10): C = A@Wt^T + bias, optional fused LN+SiLU.
// ---------------------------------------------------------------------------
template<int BM, int BN, int WARPS_M, int WARPS_N, bool FUSE_LN, bool PRED_N,
         bool OUT_BF16>
__global__ __launch_bounds__(256, 2) void bf16_gemm(
    const __nv_bfloat16* __restrict__ A, const __nv_bfloat16* __restrict__ Wt,
    const float* __restrict__ bias, const float* __restrict__ gamma,
    const float* __restrict__ beta, void* __restrict__ Cout,
    int M, int N, int K)
{
    constexpr int BK   = 16;
    constexpr int WM   = BM / WARPS_M;
    constexpr int WN   = BN / WARPS_N;
    constexpr int MI   = WM / 16;
    constexpr int NI   = WN / 8;
    constexpr int NP   = NI / 2;
    constexpr int STR  = BK + 8;
    constexpr uint32_t A_BUF = BM * STR * 2;
    constexpr uint32_t B_BUF = BN * STR * 2;

    __shared__ __align__(16) __nv_bfloat16 As[2][BM][STR];
    __shared__ __align__(16) __nv_bfloat16 Bs[2][BN][STR];
    __shared__ float red[2][BM][WARPS_N];

    const int t    = threadIdx.x;
    const int lane = t & 31;
    const int warp = t >> 5;
    const int wm   = warp % WARPS_M;
    const int wn   = warp / WARPS_M;
    const int g    = lane >> 2;
    const int c    = lane & 3;
    const int m0   = blockIdx.y * BM;
    const int n0   = FUSE_LN ? 0 : blockIdx.x * BN;

    float acc[MI][NI][4];
#pragma unroll
    for (int mI = 0; mI < MI; ++mI)
#pragma unroll
        for (int nI = 0; nI < NI; ++nI)
#pragma unroll
            for (int r = 0; r < 4; ++r) acc[mI][nI][r] = 0.f;

    const int arow = wm * WM + (lane & 15);
    const int akc  = (lane >> 4) * 8;
    const int brow = wn * WN + (lane & 7) + ((lane >> 4) << 3);
    const int bkc  = ((lane >> 3) & 1) * 8;
    const uint32_t aBase = smem_u32(&As[0][arow][akc]);
    const uint32_t bBase = smem_u32(&Bs[0][brow][bkc]);

    auto issue_tile = [&](int kt, int buf) {
        const int k0 = kt * BK;
        if (t < BM * 2) {
            const int row = t >> 1;
            const int kc  = (t & 1) * 8;
            const int gm = m0 + row;
            const bool ok = gm < M;
            const __nv_bfloat16* src = A + (ok ? ((size_t)gm * K + k0 + kc) : 0);
            cp16(&As[buf][row][kc], src, ok ? 16 : 0);
        }
#pragma unroll
        for (int i = 0; i < (BN * 2 + 255) / 256; ++i) {
            const int s = t + i * 256;
            if (s < BN * 2) {
                const int row = s >> 1;
                const int kc  = (s & 1) * 8;
                const bool ok = (!PRED_N || (n0 + row) < N);
                const __nv_bfloat16* src =
                    Wt + (ok ? ((size_t)(n0 + row) * K + k0 + kc) : 0);
                cp16(&Bs[buf][row][kc], src, ok ? 16 : 0);
            }
        }
        asm volatile("cp.async.commit_group;" ::: "memory");
    };

    const int kTiles = K / BK;
    issue_tile(0, 0);

#pragma unroll 2
    for (int kt = 0; kt < kTiles; ++kt) {
        asm volatile("cp.async.wait_group 0;" ::: "memory");
        __syncthreads();
        if (kt + 1 < kTiles) issue_tile(kt + 1, (kt + 1) & 1);
        const uint32_t aOff = (kt & 1) ? A_BUF : 0u;
        const uint32_t bOff = (kt & 1) ? B_BUF : 0u;

        uint32_t af[MI][4], bf[NI][2];
#pragma unroll
        for (int mI = 0; mI < MI; ++mI)
            ldsm_x4(af[mI][0], af[mI][1], af[mI][2], af[mI][3],
                    aBase + aOff + (uint32_t)(mI * 16 * STR * 2));
#pragma unroll
        for (int p = 0; p < NP; ++p)
            ldsm_x4(bf[2 * p][0], bf[2 * p][1], bf[2 * p + 1][0], bf[2 * p + 1][1],
                    bBase + bOff + (uint32_t)(p * 16 * STR * 2));
#pragma unroll
        for (int mI = 0; mI < MI; ++mI)
#pragma unroll
            for (int nI = 0; nI < NI; ++nI) {
                float* d = acc[mI][nI];
                asm volatile(
                    "mma.sync.aligned.m16n8k16.row.col.f32.bf16.bf16.f32 "
                    "{%0,%1,%2,%3}, {%4,%5,%6,%7}, {%8,%9}, {%0,%1,%2,%3};"
                    : "+f"(d[0]), "+f"(d[1]), "+f"(d[2]), "+f"(d[3])
                    : "r"(af[mI][0]), "r"(af[mI][1]),
                      "r"(af[mI][2]), "r"(af[mI][3]),
                      "r"(bf[nI][0]), "r"(bf[nI][1]));
            }
    }

#pragma unroll
    for (int nI = 0; nI < NI; ++nI) {
        const int col = n0 + wn * WN + nI * 8 + 2 * c;
        float b0 = 0.f, b1 = 0.f;
        if (!PRED_N || col < N) { b0 = bias[col]; b1 = bias[col + 1]; }
#pragma unroll
        for (int mI = 0; mI < MI; ++mI) {
            acc[mI][nI][0] += b0; acc[mI][nI][1] += b1;
            acc[mI][nI][2] += b0; acc[mI][nI][3] += b1;
        }
    }

    float mean_[MI][2], rstd_[MI][2];
    if (FUSE_LN) {
#pragma unroll
        for (int mI = 0; mI < MI; ++mI)
#pragma unroll
            for (int h = 0; h < 2; ++h) {
                float s = 0.f, s2 = 0.f;
#pragma unroll
                for (int nI = 0; nI < NI; ++nI) {
                    const float v0 = acc[mI][nI][2 * h];
                    const float v1 = acc[mI][nI][2 * h + 1];
                    s += v0 + v1; s2 += v0 * v0 + v1 * v1;
                }
                s  += __shfl_xor_sync(0xffffffffu, s, 1);
                s  += __shfl_xor_sync(0xffffffffu, s, 2);
                s2 += __shfl_xor_sync(0xffffffffu, s2, 1);
                s2 += __shfl_xor_sync(0xffffffffu, s2, 2);
                if (c == 0) {
                    const int lr = wm * WM + mI * 16 + h * 8 + g;
                    red[0][lr][wn] = s;
                    red[1][lr][wn] = s2;
                }
            }
        __syncthreads();
#pragma unroll
        for (int mI = 0; mI < MI; ++mI)
#pragma unroll
            for (int h = 0; h < 2; ++h) {
                const int lr = wm * WM + mI * 16 + h * 8 + g;
                float s = 0.f, s2 = 0.f;
#pragma unroll
                for (int w = 0; w < WARPS_N; ++w) { s += red[0][lr][w]; s2 += red[1][lr][w]; }
                const float mean = s / (float)N;
                const float var  = s2 / (float)N - mean * mean;
                mean_[mI][h] = mean;
                rstd_[mI][h] = rsqrtf(var + 1e-5f);
            }
    }

#pragma unroll
    for (int nI = 0; nI < NI; ++nI) {
        const int col = n0 + wn * WN + nI * 8 + 2 * c;
        if (PRED_N && col >= N) continue;
        float ga0 = 0.f, ga1 = 0.f, be0 = 0.f, be1 = 0.f;
        if (FUSE_LN) { ga0 = gamma[col]; ga1 = gamma[col + 1];
                       be0 = beta[col];  be1 = beta[col + 1]; }
#pragma unroll
        for (int mI = 0; mI < MI; ++mI)
#pragma unroll
            for (int h = 0; h < 2; ++h) {
                const int m = m0 + wm * WM + mI * 16 + h * 8 + g;
                if (m >= M) continue;
                float v0 = acc[mI][nI][2 * h];
                float v1 = acc[mI][nI][2 * h + 1];
                if (FUSE_LN) {
                    v0 = (v0 - mean_[mI][h]) * rstd_[mI][h] * ga0 + be0;
                    v1 = (v1 - mean_[mI][h]) * rstd_[mI][h] * ga1 + be1;
                    v0 = v0 / (1.f + __expf(-v0));
                    v1 = v1 / (1.f + __expf(-v1));
                }
                if (OUT_BF16) {
                    __nv_bfloat162 o = __floats2bfloat162_rn(v0, v1);
                    *reinterpret_cast<__nv_bfloat162*>(
                        &((__nv_bfloat16*)Cout)[(size_t)m * N + col]) = o;
                } else {
                    *reinterpret_cast<float2*>(
                        &((float*)Cout)[(size_t)m * N + col]) = make_float2(v0, v1);
                }
            }
    }
}

// ---------------------------------------------------------------------------
__global__ void f32_to_bf16_kernel(const float* __restrict__ in,
                                   __nv_bfloat16* __restrict__ out, size_t n)
{
    const size_t i = ((size_t)blockIdx.x * blockDim.x + threadIdx.x) * 2;
    if (i < n) {
        float2 v = *reinterpret_cast<const float2*>(&in[i]);
        *reinterpret_cast<__nv_bfloat162*>(&out[i]) = __floats2bfloat162_rn(v.x, v.y);
    }
}

// All three weight transposes in one launch.
__global__ void conv_all_kernel(const float* __restrict__ w1,
                                const float* __restrict__ w2,
                                const float* __restrict__ w3,
                                __nv_bfloat16* __restrict__ wt1,
                                __nv_bfloat16* __restrict__ wt2,
                                __nv_bfloat16* __restrict__ wt3)
{
    const int idx = blockIdx.x * blockDim.x + threadIdx.x;
    if (idx < 256 * 256) {
        const int k = idx >> 8, n = idx & 255;
        wt1[n * 256 + k] = __float2bfloat16(w1[idx]);
    } else if (idx < 256 * 256 + 256 * 128) {
        const int i = idx - 256 * 256;
        const int k = i >> 7, n = i & 127;
        wt2[n * 256 + k] = __float2bfloat16(w2[i]);
    } else if (idx < 256 * 256 + 256 * 128 + 128 * 300) {
        const int i = idx - (256 * 256 + 256 * 128);
        const int k = i / 300, n = i % 300;
        wt3[n * 128 + k] = __float2bfloat16(w3[i]);
    }
}

// seg + sf zeroing in one launch.
__global__ void prologue_kernel(const int* __restrict__ batch, int N, int B,
                                float* __restrict__ sf, int sfn)
{
    const int i = blockIdx.x * blockDim.x + threadIdx.x;
    if (i < sfn) sf[i] = 0.f;
    if (i <= B) {
        int lo = 0, hi = N;
        while (lo < hi) {
            int mid = (lo + hi) >> 1;
            if (batch[mid] < i) lo = mid + 1; else hi = mid;
        }
        g_seg[i] = lo;
    }
}

// ---------------------------------------------------------------------------
// Small SGEMM (B=256 rows): 64x64, BK=16, 4x4 microtile. Optional split-A.
// ---------------------------------------------------------------------------
__global__ __launch_bounds__(256) void sgemm_small(
    const float* __restrict__ A, const float* __restrict__ A2, int K1,
    const float* __restrict__ W,
    const float* __restrict__ bias, const float* __restrict__ residual,
    float* __restrict__ C, int M, int N, int K)
{
    __shared__ float As[16][64];
    __shared__ float Bs[16][68];

    const int t  = threadIdx.x;
    const int tx = t & 15;
    const int ty = t >> 4;
    const int n0 = blockIdx.x * 64;
    const int m0 = blockIdx.y * 64;
    const int K2 = K - K1;

    float acc[4][4];
#pragma unroll
    for (int i = 0; i < 4; ++i)
#pragma unroll
        for (int j = 0; j < 4; ++j) acc[i][j] = 0.f;

    const int kTiles = (K + 15) / 16;
    for (int kt = 0; kt < kTiles; ++kt) {
        const int k0 = kt * 16;
        {
            const int row = t >> 2;
            const int c4  = (t & 3) * 4;
            const int gm = m0 + row, gk = k0 + c4;
            float4 v = make_float4(0.f,0.f,0.f,0.f);
            if (gm < M && gk < K) {
                if (gk < K1)
                    v = *reinterpret_cast<const float4*>(&A[(size_t)gm * K1 + gk]);
                else
                    v = *reinterpret_cast<const float4*>(&A2[(size_t)gm * K2 + (gk - K1)]);
            }
            As[c4 + 0][row] = v.x; As[c4 + 1][row] = v.y;
            As[c4 + 2][row] = v.z; As[c4 + 3][row] = v.w;
        }
        {
            const int rowk = t >> 4;
            const int c4   = (t & 15) * 4;
            const int gk = k0 + rowk, gn = n0 + c4;
            float4 v = make_float4(0.f,0.f,0.f,0.f);
            if (gk < K && gn < N)
                v = *reinterpret_cast<const float4*>(&W[(size_t)gk * N + gn]);
            *reinterpret_cast<float4*>(&Bs[rowk][c4]) = v;
        }
        __syncthreads();

#pragma unroll
        for (int kk = 0; kk < 16; ++kk) {
            float4 av = *reinterpret_cast<const float4*>(&As[kk][ty * 4]);
            float4 bv = *reinterpret_cast<const float4*>(&Bs[kk][tx * 4]);
            float a[4] = {av.x,av.y,av.z,av.w};
            float b[4] = {bv.x,bv.y,bv.z,bv.w};
#pragma unroll
            for (int i = 0; i < 4; ++i)
#pragma unroll
                for (int j = 0; j < 4; ++j)
                    acc[i][j] = fmaf(a[i], b[j], acc[i][j]);
        }
        __syncthreads();
    }

#pragma unroll
    for (int i = 0; i < 4; ++i) {
        const int m = m0 + ty * 4 + i;
        if (m >= M) continue;
#pragma unroll
        for (int j = 0; j < 4; ++j) {
            const int n = n0 + tx * 4 + j;
            if (n >= N) continue;
            float v = acc[i][j] + bias[n];
            if (residual) v += residual[(size_t)m * N + n];
            C[(size_t)m * N + n] = v;
        }
    }
}

// ---------------------------------------------------------------------------
__global__ void ln_silu_kernel(float* __restrict__ X, const float* __restrict__ g,
                               const float* __restrict__ b, int W, int do_silu)
{
    const int row = blockIdx.x;
    const int t = threadIdx.x;
    const int lane = t & 31, warp = t >> 5, nw = W >> 5;
    __shared__ float red[16];

    float x = X[(size_t)row * W + t];

    float s = x;
#pragma unroll
    for (int o = 16; o > 0; o >>= 1) s += __shfl_xor_sync(0xffffffffu, s, o);
    if (lane == 0) red[warp] = s;
    __syncthreads();
    float v = (lane < nw) ? red[lane] : 0.f;
#pragma unroll
    for (int o = 16; o > 0; o >>= 1) v += __shfl_xor_sync(0xffffffffu, v, o);
    const float mean = v / (float)W;
    __syncthreads();

    const float dx = x - mean;
    float s2 = dx * dx;
#pragma unroll
    for (int o = 16; o > 0; o >>= 1) s2 += __shfl_xor_sync(0xffffffffu, s2, o);
    if (lane == 0) red[warp] = s2;
    __syncthreads();
    float v2 = (lane < nw) ? red[lane] : 0.f;
#pragma unroll
    for (int o = 16; o > 0; o >>= 1) v2 += __shfl_xor_sync(0xffffffffu, v2, o);
    const float var = v2 / (float)W;

    float y = dx * rsqrtf(var + 1e-5f) * g[t] + b[t];
    if (do_silu) y = y * (1.0f / (1.0f + expf(-y)));
    X[(size_t)row * W + t] = y;
}

// ---------------------------------------------------------------------------
// Structure-factor accumulation; ff in bf16; node loop unrolled x2.
// ---------------------------------------------------------------------------
__global__ void accum_kernel(const __nv_bfloat16* __restrict__ ff,
                             const float* __restrict__ pos,
                             const float* __restrict__ hkl,
                             float* __restrict__ sf, int nchunks)
{
    const int b = blockIdx.x;
    const int chunk = blockIdx.y;
    const int j = threadIdx.x;
    if (j >= 300) return;

    const int s = g_seg[b], e = g_seg[b + 1];
    const int len = e - s;
    if (len <= 0) return;
    const int per = (len + nchunks - 1) / nchunks;
    const int n0 = s + chunk * per;
    const int n1 = (n0 + per < e) ? (n0 + per) : e;
    if (n0 >= e) return;

    const float hx = hkl[j * 3 + 0], hy = hkl[j * 3 + 1], hz = hkl[j * 3 + 2];
    float rj = 0.f, ij = 0.f;
    const float TWO_PI = 6.283185307179586f;

    int n = n0;
    for (; n + 1 < n1; n += 2) {
        const float px0 = __ldg(&pos[n * 3 + 0]);
        const float py0 = __ldg(&pos[n * 3 + 1]);
        const float pz0 = __ldg(&pos[n * 3 + 2]);
        const float px1 = __ldg(&pos[n * 3 + 3]);
        const float py1 = __ldg(&pos[n * 3 + 4]);
        const float pz1 = __ldg(&pos[n * 3 + 5]);
        const float f0 = __bfloat162float(ff[(size_t)n * 300 + j]);
        const float f1 = __bfloat162float(ff[(size_t)(n + 1) * 300 + j]);
        float d0 = fmaf(px0, hx, fmaf(py0, hy, pz0 * hz));
        float d1 = fmaf(px1, hx, fmaf(py1, hy, pz1 * hz));
        d0 -= rintf(d0);
        d1 -= rintf(d1);
        float sn0, cs0, sn1, cs1;
        __sincosf(TWO_PI * d0, &sn0, &cs0);
        __sincosf(TWO_PI * d1, &sn1, &cs1);
        rj = fmaf(f0, cs0, rj); ij = fmaf(f0, sn0, ij);
        rj = fmaf(f1, cs1, rj); ij = fmaf(f1, sn1, ij);
    }
    if (n < n1) {
        const float px = __ldg(&pos[n * 3 + 0]);
        const float py = __ldg(&pos[n * 3 + 1]);
        const float pz = __ldg(&pos[n * 3 + 2]);
        const float f = __bfloat162float(ff[(size_t)n * 300 + j]);
        float d = fmaf(px, hx, fmaf(py, hy, pz * hz));
        d -= rintf(d);
        float sn, cs;
        __sincosf(TWO_PI * d, &sn, &cs);
        rj = fmaf(f, cs, rj);
        ij = fmaf(f, sn, ij);
    }
    atomicAdd(&sf[b * 600 + 2 * j + 0], rj);
    atomicAdd(&sf[b * 600 + 2 * j + 1], ij);
}

// ---------------------------------------------------------------------------
extern "C" void kernel_launch(void* const* d_in, const int* in_sizes, int n_in,
                              void* d_out, int out_size)
{
    const float* graph  = (const float*)d_in[0];
    const float* nodef  = (const float*)d_in[1];
    const float* pos    = (const float*)d_in[2];
    const int*   batch  = (const int*)  d_in[3];
    const float* hkl    = (const float*)d_in[4];
    const float* ff_w1  = (const float*)d_in[5];
    const float* ff_b1  = (const float*)d_in[6];
    const float* ff_g1  = (const float*)d_in[7];
    const float* ff_bb1 = (const float*)d_in[8];
    const float* ff_w2  = (const float*)d_in[9];
    const float* ff_b2  = (const float*)d_in[10];
    const float* ff_g2  = (const float*)d_in[11];
    const float* ff_bb2 = (const float*)d_in[12];
    const float* ff_w3  = (const float*)d_in[13];
    const float* ff_b3  = (const float*)d_in[14];
    const float* dn_w1  = (const float*)d_in[15];
    const float* dn_b1  = (const float*)d_in[16];
    const float* dn_g1  = (const float*)d_in[17];
    const float* dn_bb1 = (const float*)d_in[18];
    const float* dn_w2  = (const float*)d_in[19];
    const float* dn_b2  = (const float*)d_in[20];
    const float* dn_g2  = (const float*)d_in[21];
    const float* dn_bb2 = (const float*)d_in[22];
    const float* dn_w3  = (const float*)d_in[23];
    const float* dn_b3  = (const float*)d_in[24];
    const float* fn_w1  = (const float*)d_in[25];
    const float* fn_b1  = (const float*)d_in[26];
    const float* fn_g   = (const float*)d_in[27];
    const float* fn_bb  = (const float*)d_in[28];
    const float* fn_w2  = (const float*)d_in[29];
    const float* fn_b2  = (const float*)d_in[30];
    float* out = (float*)d_out;

    const int N = in_sizes[3];
    const int B = in_sizes[0] / 512;

    __nv_bfloat16 *nf, *s1b, *s2b, *wt1, *wt2, *wt3, *ffb;
    float *sf, *dd1, *dd2, *dd3, *f1;
    cudaGetSymbolAddress((void**)&nf,   g_nf);
    cudaGetSymbolAddress((void**)&s1b,  g_s1b);
    cudaGetSymbolAddress((void**)&s2b,  g_s2b);
    cudaGetSymbolAddress((void**)&wt1,  g_wt1);
    cudaGetSymbolAddress((void**)&wt2,  g_wt2);
    cudaGetSymbolAddress((void**)&wt3,  g_wt3);
    cudaGetSymbolAddress((void**)&ffb,  g_ffb);
    cudaGetSymbolAddress((void**)&sf,   g_sf);
    cudaGetSymbolAddress((void**)&dd1,  g_d1);
    cudaGetSymbolAddress((void**)&dd2,  g_d2);
    cudaGetSymbolAddress((void**)&dd3,  g_d3);
    cudaGetSymbolAddress((void**)&f1,   g_f1);

    const int gy = (N + 63) / 64;
    const size_t nfe = (size_t)N * 256;

    // --- prologue (3 launches) ---
    f32_to_bf16_kernel<<<(int)((nfe / 2 + 255) / 256), 256>>>(nodef, nf, nfe);
    const int conv_total = 256 * 256 + 256 * 128 + 128 * 300;
    conv_all_kernel<<<(conv_total + 255) / 256, 256>>>(ff_w1, ff_w2, ff_w3,
                                                       wt1, wt2, wt3);
    prologue_kernel<<<(B * 600 + 255) / 256, 256>>>(batch, N, B, sf, B * 600);

    // --- node MLP (v10 path, unchanged) ---
    bf16_gemm<64, 256, 2, 4, true,  false, true ><<<dim3(1, gy), 256>>>(
        nf,  wt1, ff_b1, ff_g1, ff_bb1, s1b, N, 256, 256);
    bf16_gemm<64, 128, 4, 2, true,  false, true ><<<dim3(1, gy), 256>>>(
        s1b, wt2, ff_b2, ff_g2, ff_bb2, s2b, N, 128, 256);
    bf16_gemm<64, 64,  4, 2, false, true,  true ><<<dim3(5, gy), 256>>>(
        s2b, wt3, ff_b3, nullptr, nullptr, ffb, N, 300, 128);

    // --- structure factors (ff in bf16) ---
    const int CHUNKS = 8;
    accum_kernel<<<dim3(B, CHUNKS), 320>>>(ffb, pos, hkl, sf, CHUNKS);

    // --- diffraction net (B rows) ---
    sgemm_small<<<dim3(8, (B + 63) / 64), 256>>>(sf, nullptr, 600,
        dn_w1, dn_b1, nullptr, dd1, B, 512, 600);
    ln_silu_kernel<<<B, 512>>>(dd1, dn_g1, dn_bb1, 512, 1);
    sgemm_small<<<dim3(4, (B + 63) / 64), 256>>>(dd1, nullptr, 512,
        dn_w2, dn_b2, nullptr, dd2, B, 256, 512);
    ln_silu_kernel<<<B, 256>>>(dd2, dn_g2, dn_bb2, 256, 1);
    sgemm_small<<<dim3(8, (B + 63) / 64), 256>>>(dd2, nullptr, 256,
        dn_w3, dn_b3, nullptr, dd3, B, 512, 256);

    // --- fusion net: concat folded in (split-A), then LN, then final+res ---
    sgemm_small<<<dim3(8, (B + 63) / 64), 256>>>(graph, dd3, 512,
        fn_w1, fn_b1, nullptr, f1, B, 512, 1024);
    ln_silu_kernel<<<B, 512>>>(f1, fn_g, fn_bb, 512, 1);
    sgemm_small<<<dim3(8, (B + 63) / 64), 256>>>(f1, nullptr, 512,
        fn_w2, fn_b2, graph, out, B, 512, 512);
}